// round 2
// baseline (speedup 1.0000x reference)
#include <cuda_runtime.h>
#include <math.h>

// ---------------------------------------------------------------------------
// Fused CNN: conv1(1->32,3x3,same,relu)+pool2 -> conv2(32->64)+pool2 ->
//            conv3(64->64) -> dense(3136->64,relu) -> dense(64->10)+softmax
// B=2048. All fp32. Packed fma.rn.f32x2 in the hot loops (exact fp32 rounding).
// Intermediates channel-first: P1[b][32][14][14], P2[b][64][7][7].
// ---------------------------------------------------------------------------

#define BATCH 2048

__device__ float g_p1[BATCH * 32 * 14 * 14];   // 51.4 MB
__device__ float g_p2[BATCH * 64 * 7 * 7];     // 25.7 MB

// ---- packed f32x2 helpers (exact fp32 semantics, 2 FMA per instruction) ----
__device__ __forceinline__ unsigned long long pack2(float x) {
    unsigned long long r;
    asm("mov.b64 %0, {%1, %1};" : "=l"(r) : "f"(x));
    return r;
}
__device__ __forceinline__ void ffma2(unsigned long long& d,
                                      unsigned long long a,
                                      unsigned long long b) {
    asm("fma.rn.f32x2 %0, %1, %2, %0;" : "+l"(d) : "l"(a), "l"(b));
}
__device__ __forceinline__ void unpack2(unsigned long long v, float& lo, float& hi) {
    asm("mov.b64 {%0, %1}, %2;" : "=f"(lo), "=f"(hi) : "l"(v));
}

// ---------------------------------------------------------------------------
// K1: conv1 (1->32, 3x3 SAME) + relu + maxpool2  -> P1[b][32][14][14]
// One CTA per image, 256 threads.
// ---------------------------------------------------------------------------
__global__ void __launch_bounds__(256)
k1_conv1(const float* __restrict__ x, const float* __restrict__ w1,
         const float* __restrict__ b1) {
    __shared__ float xs[30 * 30];   // zero-padded input
    __shared__ float w1s[9 * 32];
    __shared__ float b1s[32];

    const int b   = blockIdx.x;
    const int tid = threadIdx.x;

    for (int i = tid; i < 900; i += 256) xs[i] = 0.0f;
    for (int i = tid; i < 288; i += 256) w1s[i] = w1[i];
    if (tid < 32) b1s[tid] = b1[tid];
    __syncthreads();

    const float* xb = x + b * 784;
    for (int i = tid; i < 784; i += 256) {
        int y = i / 28, xx = i % 28;
        xs[(y + 1) * 30 + xx + 1] = xb[i];
    }
    __syncthreads();

    const int oc0  = tid >> 5;   // 0..7
    const int lane = tid & 31;
    float* pb = g_p1 + (size_t)b * 32 * 196;

    for (int oc = oc0; oc < 32; oc += 8) {
        float wk[9];
#pragma unroll
        for (int t = 0; t < 9; t++) wk[t] = w1s[t * 32 + oc];
        const float bias = b1s[oc];

        for (int p = lane; p < 196; p += 32) {
            int py = p / 14, px = p % 14;
            float m = 0.0f;     // relu outputs are >= 0
#pragma unroll
            for (int dy = 0; dy < 2; dy++) {
#pragma unroll
                for (int dx = 0; dx < 2; dx++) {
                    int y = 2 * py + dy, xx = 2 * px + dx;
                    float s = bias;
#pragma unroll
                    for (int ky = 0; ky < 3; ky++)
#pragma unroll
                        for (int kx = 0; kx < 3; kx++)
                            s = fmaf(xs[(y + ky) * 30 + xx + kx], wk[ky * 3 + kx], s);
                    m = fmaxf(m, fmaxf(s, 0.0f));
                }
            }
            pb[oc * 196 + p] = m;
        }
    }
}

// ---------------------------------------------------------------------------
// K2: conv2 (32->64, 3x3 SAME) + relu + maxpool2  -> P2[b][64][7][7]
// One CTA per image, 416 threads (392 compute workers: 8 oc-groups x 49 pools).
// Each worker: 4 conv positions (2x2 pool window) x 8 output channels.
// smem: A[32][16][16] zero-padded acts (32KB) + w2[9][32][64] (72KB).
// ---------------------------------------------------------------------------
__global__ void __launch_bounds__(416, 2)
k2_conv2(const float* __restrict__ w2, const float* __restrict__ b2) {
    extern __shared__ float sm2[];
    float* As  = sm2;           // 8192 floats
    float* w2s = sm2 + 8192;    // 18432 floats
    float* b2s = w2s + 18432;   // 64 floats

    const int b   = blockIdx.x;
    const int tid = threadIdx.x;

    for (int i = tid; i < 8192; i += 416) As[i] = 0.0f;
    for (int i = tid; i < 18432; i += 416) w2s[i] = w2[i];
    if (tid < 64) b2s[tid] = b2[tid];
    __syncthreads();

    const float* pin = g_p1 + (size_t)b * 6272;
    for (int i = tid; i < 6272; i += 416) {
        int ic = i / 196, r = i % 196;
        int y = r / 14, xx = r % 14;
        As[ic * 256 + (y + 1) * 16 + xx + 1] = pin[i];
    }
    __syncthreads();

    if (tid < 392) {
        const int ocg = tid / 49;          // 0..7  -> oc base = ocg*8
        const int p   = tid % 49;
        const int py  = p / 7, px = p % 7;

        unsigned long long acc[4][4];      // [pos(dy*2+dx)][oc-pair]
#pragma unroll
        for (int i = 0; i < 4; i++)
#pragma unroll
            for (int j = 0; j < 4; j++) acc[i][j] = 0ULL;

#pragma unroll
        for (int ky = 0; ky < 3; ky++) {
#pragma unroll
            for (int kx = 0; kx < 3; kx++) {
                const float* ap = As + (2 * py + ky) * 16 + (2 * px + kx);
                const ulonglong2* wp = reinterpret_cast<const ulonglong2*>(
                    w2s + (ky * 3 + kx) * 32 * 64 + ocg * 8);
#pragma unroll 4
                for (int ic = 0; ic < 32; ic++) {
                    unsigned long long a00 = pack2(ap[0]);
                    unsigned long long a01 = pack2(ap[1]);
                    unsigned long long a10 = pack2(ap[16]);
                    unsigned long long a11 = pack2(ap[17]);
                    ulonglong2 w0  = wp[0];
                    ulonglong2 w1v = wp[1];
                    ffma2(acc[0][0], a00, w0.x);  ffma2(acc[0][1], a00, w0.y);
                    ffma2(acc[0][2], a00, w1v.x); ffma2(acc[0][3], a00, w1v.y);
                    ffma2(acc[1][0], a01, w0.x);  ffma2(acc[1][1], a01, w0.y);
                    ffma2(acc[1][2], a01, w1v.x); ffma2(acc[1][3], a01, w1v.y);
                    ffma2(acc[2][0], a10, w0.x);  ffma2(acc[2][1], a10, w0.y);
                    ffma2(acc[2][2], a10, w1v.x); ffma2(acc[2][3], a10, w1v.y);
                    ffma2(acc[3][0], a11, w0.x);  ffma2(acc[3][1], a11, w0.y);
                    ffma2(acc[3][2], a11, w1v.x); ffma2(acc[3][3], a11, w1v.y);
                    ap += 256;
                    wp += 16;   // 64 floats = 16 x 16B
                }
            }
        }

        // bias + relu + 2x2 max-pool, store channel-first
        float* pout = g_p2 + (size_t)b * 64 * 49;
#pragma unroll
        for (int pr = 0; pr < 4; pr++) {
            int oc_lo = ocg * 8 + pr * 2;
            float blo = b2s[oc_lo], bhi = b2s[oc_lo + 1];
            float mlo = 0.0f, mhi = 0.0f;
#pragma unroll
            for (int pos = 0; pos < 4; pos++) {
                float lo, hi;
                unpack2(acc[pos][pr], lo, hi);
                mlo = fmaxf(mlo, fmaxf(lo + blo, 0.0f));
                mhi = fmaxf(mhi, fmaxf(hi + bhi, 0.0f));
            }
            pout[oc_lo * 49 + p]       = mlo;
            pout[(oc_lo + 1) * 49 + p] = mhi;
        }
    }
}

// ---------------------------------------------------------------------------
// K3: conv3 (64->64, 3x3 SAME, relu) + dense1(3136->64, relu)
//     + dense2(64->10) + softmax.  2 images per CTA, 256 threads.
// smem: w3[9][64][64] (144KB) + padded acts 2x[64][9][9] + C3 2x[3136] + misc.
// ---------------------------------------------------------------------------
__global__ void __launch_bounds__(256, 1)
k3_rest(const float* __restrict__ w3, const float* __restrict__ b3,
        const float* __restrict__ wd1, const float* __restrict__ bd1,
        const float* __restrict__ wd2, const float* __restrict__ bd2,
        float* __restrict__ out) {
    extern __shared__ float sm3[];
    float* w3s = sm3;               // 36864
    float* As  = w3s + 36864;       // 2 * 64*81 = 10368 (zero-padded)
    float* Cs  = As + 10368;        // 2 * 3136  = 6272 (NHWC-flattened conv3 out)
    float* b3s = Cs + 6272;         // 64
    float* red = b3s + 64;          // 256
    float* hs  = red + 256;         // 128
    // total 53952 floats = 215808 bytes

    const int tid = threadIdx.x;
    const int b0  = blockIdx.x * 2;

    for (int i = tid; i < 36864; i += 256) w3s[i] = w3[i];
    for (int i = tid; i < 10368; i += 256) As[i] = 0.0f;
    if (tid < 64) b3s[tid] = b3[tid];
    __syncthreads();

#pragma unroll
    for (int img = 0; img < 2; img++) {
        const float* pin = g_p2 + (size_t)(b0 + img) * 3136;
        for (int i = tid; i < 3136; i += 256) {
            int ic = i / 49, r = i % 49;
            int y = r / 7, xx = r % 7;
            As[img * 5184 + ic * 81 + (y + 1) * 9 + xx + 1] = pin[i];
        }
    }
    __syncthreads();

    // ---- conv3: 224 workers = 2 img x 7 rows x 16 oc-groups (4 oc each) ----
    if (tid < 224) {
        const int img = tid / 112;
        const int r   = tid % 112;
        const int row = r >> 4;       // 0..6
        const int ocg = r & 15;       // oc base = ocg*4

        unsigned long long acc[7][2];
#pragma unroll
        for (int i = 0; i < 7; i++) { acc[i][0] = 0ULL; acc[i][1] = 0ULL; }

        const float* Ab = As + img * 5184;
#pragma unroll
        for (int ky = 0; ky < 3; ky++) {
#pragma unroll
            for (int kx = 0; kx < 3; kx++) {
                const float* ap = Ab + (row + ky) * 9 + kx;
                const ulonglong2* wp = reinterpret_cast<const ulonglong2*>(
                    w3s + (ky * 3 + kx) * 64 * 64 + ocg * 4);
#pragma unroll 4
                for (int ic = 0; ic < 64; ic++) {
                    ulonglong2 wv = wp[0];
                    unsigned long long a[7];
#pragma unroll
                    for (int xp = 0; xp < 7; xp++) a[xp] = pack2(ap[xp]);
#pragma unroll
                    for (int xp = 0; xp < 7; xp++) {
                        ffma2(acc[xp][0], a[xp], wv.x);
                        ffma2(acc[xp][1], a[xp], wv.y);
                    }
                    ap += 81;
                    wp += 16;   // 64 floats
                }
            }
        }

        const int oc0 = ocg * 4;
        float bb[4];
#pragma unroll
        for (int j = 0; j < 4; j++) bb[j] = b3s[oc0 + j];
        float* cb = Cs + img * 3136;
#pragma unroll
        for (int xp = 0; xp < 7; xp++) {
            float v0, v1, v2, v3;
            unpack2(acc[xp][0], v0, v1);
            unpack2(acc[xp][1], v2, v3);
            int base = (row * 7 + xp) * 64 + oc0;
            cb[base + 0] = fmaxf(v0 + bb[0], 0.0f);
            cb[base + 1] = fmaxf(v1 + bb[1], 0.0f);
            cb[base + 2] = fmaxf(v2 + bb[2], 0.0f);
            cb[base + 3] = fmaxf(v3 + bb[3], 0.0f);
        }
    }
    __syncthreads();

    // ---- dense1: 3136 -> 64, relu.  2-way K split, 256 workers ----
    {
        const int oc  = tid & 63;
        const int img = (tid >> 6) & 1;
        const int kh  = tid >> 7;
        const float* c   = Cs + img * 3136 + kh * 1568;
        const float* wdp = wd1 + (size_t)(kh * 1568) * 64 + oc;
        float a = 0.0f;
#pragma unroll 4
        for (int k = 0; k < 1568; k++)
            a = fmaf(c[k], __ldg(wdp + (size_t)k * 64), a);
        red[tid] = a;
    }
    __syncthreads();
    if (tid < 128) {
        int oc = tid & 63, img = tid >> 6;
        float v = red[tid] + red[tid + 128] + bd1[oc];
        hs[img * 64 + oc] = fmaxf(v, 0.0f);
    }
    __syncthreads();

    // ---- dense2 + softmax (tiny; 1 thread per image) ----
    if (tid < 2) {
        const int img = tid;
        float lg[10];
#pragma unroll
        for (int c2 = 0; c2 < 10; c2++) {
            float s = bd2[c2];
#pragma unroll
            for (int j = 0; j < 64; j++)
                s = fmaf(hs[img * 64 + j], wd2[j * 10 + c2], s);
            lg[c2] = s;
        }
        float m = lg[0];
#pragma unroll
        for (int c2 = 1; c2 < 10; c2++) m = fmaxf(m, lg[c2]);
        float se = 0.0f;
#pragma unroll
        for (int c2 = 0; c2 < 10; c2++) { lg[c2] = expf(lg[c2] - m); se += lg[c2]; }
        float inv = 1.0f / se;
        float* o = out + (size_t)(b0 + img) * 10;
#pragma unroll
        for (int c2 = 0; c2 < 10; c2++) o[c2] = lg[c2] * inv;
    }
}

// ---------------------------------------------------------------------------
extern "C" void kernel_launch(void* const* d_in, const int* in_sizes, int n_in,
                              void* d_out, int out_size) {
    const float* x   = (const float*)d_in[0];
    const float* w1  = (const float*)d_in[1];
    const float* b1  = (const float*)d_in[2];
    const float* w2  = (const float*)d_in[3];
    const float* b2  = (const float*)d_in[4];
    const float* w3  = (const float*)d_in[5];
    const float* b3  = (const float*)d_in[6];
    const float* wd1 = (const float*)d_in[7];
    const float* bd1 = (const float*)d_in[8];
    const float* wd2 = (const float*)d_in[9];
    const float* bd2 = (const float*)d_in[10];
    float* out = (float*)d_out;

    const int smem2 = (8192 + 18432 + 64) * 4;                      // 106752
    const int smem3 = (36864 + 10368 + 6272 + 64 + 256 + 128) * 4;  // 215808

    cudaFuncSetAttribute(k2_conv2, cudaFuncAttributeMaxDynamicSharedMemorySize, smem2);
    cudaFuncSetAttribute(k3_rest,  cudaFuncAttributeMaxDynamicSharedMemorySize, smem3);

    k1_conv1<<<BATCH, 256>>>(x, w1, b1);
    k2_conv2<<<BATCH, 416, smem2>>>(w2, b2);
    k3_rest<<<BATCH / 2, 256, smem3>>>(w3, b3, wd1, bd1, wd2, bd2, out);
}

// round 3
// speedup vs baseline: 1.3141x; 1.3141x over previous
#include <cuda_runtime.h>
#include <math.h>

// ---------------------------------------------------------------------------
// Fused CNN: conv1(1->32,3x3,same,relu)+pool2 -> conv2(32->64)+pool2 ->
//            conv3(64->64) -> dense(3136->64,relu) -> dense(64->10)+softmax
// B=2048, fp32, packed fma.rn.f32x2 in hot loops (bit-exact fp32 rounding).
// ---------------------------------------------------------------------------

#define BATCH 2048

__device__ float g_p1[BATCH * 32 * 14 * 14];   // conv1+pool out, channel-first
__device__ float g_p2[BATCH * 64 * 7 * 7];     // conv2+pool out, channel-first
__device__ float g_c3[BATCH * 3136];           // conv3 out, NHWC-flattened

// ---- packed f32x2 helpers ----
__device__ __forceinline__ unsigned long long pack2(float x) {
    unsigned long long r;
    asm("mov.b64 %0, {%1, %1};" : "=l"(r) : "f"(x));
    return r;
}
__device__ __forceinline__ void ffma2(unsigned long long& d,
                                      unsigned long long a,
                                      unsigned long long b) {
    asm("fma.rn.f32x2 %0, %1, %2, %0;" : "+l"(d) : "l"(a), "l"(b));
}
__device__ __forceinline__ void unpack2(unsigned long long v, float& lo, float& hi) {
    asm("mov.b64 {%0, %1}, %2;" : "=f"(lo), "=f"(hi) : "l"(v));
}

// ---------------------------------------------------------------------------
// K1: conv1 (1->32, 3x3 SAME) + relu + maxpool2  -> g_p1[b][32][14][14]
// ---------------------------------------------------------------------------
__global__ void __launch_bounds__(256)
k1_conv1(const float* __restrict__ x, const float* __restrict__ w1,
         const float* __restrict__ b1) {
    __shared__ float xs[30 * 30];
    __shared__ float w1s[9 * 32];
    __shared__ float b1s[32];

    const int b   = blockIdx.x;
    const int tid = threadIdx.x;

    for (int i = tid; i < 900; i += 256) xs[i] = 0.0f;
    for (int i = tid; i < 288; i += 256) w1s[i] = w1[i];
    if (tid < 32) b1s[tid] = b1[tid];
    __syncthreads();

    const float* xb = x + b * 784;
    for (int i = tid; i < 784; i += 256) {
        int y = i / 28, xx = i % 28;
        xs[(y + 1) * 30 + xx + 1] = xb[i];
    }
    __syncthreads();

    const int oc0  = tid >> 5;
    const int lane = tid & 31;
    float* pb = g_p1 + (size_t)b * 32 * 196;

    for (int oc = oc0; oc < 32; oc += 8) {
        float wk[9];
#pragma unroll
        for (int t = 0; t < 9; t++) wk[t] = w1s[t * 32 + oc];
        const float bias = b1s[oc];

        for (int p = lane; p < 196; p += 32) {
            int py = p / 14, px = p % 14;
            float m = 0.0f;
#pragma unroll
            for (int dy = 0; dy < 2; dy++) {
#pragma unroll
                for (int dx = 0; dx < 2; dx++) {
                    int y = 2 * py + dy, xx = 2 * px + dx;
                    float s = bias;
#pragma unroll
                    for (int ky = 0; ky < 3; ky++)
#pragma unroll
                        for (int kx = 0; kx < 3; kx++)
                            s = fmaf(xs[(y + ky) * 30 + xx + kx], wk[ky * 3 + kx], s);
                    m = fmaxf(m, fmaxf(s, 0.0f));
                }
            }
            pb[oc * 196 + p] = m;
        }
    }
}

// ---------------------------------------------------------------------------
// K2: conv2 (32->64) + relu + maxpool2 -> g_p2[b][64][7][7]
// Split-parity act layout: x -> (x&1)*8 + (x>>1)  (removes 2-way bank conflicts
// from the stride-2 conv reads).
// ---------------------------------------------------------------------------
__device__ __forceinline__ int axm(int x) { return ((x & 1) << 3) | (x >> 1); }

__global__ void __launch_bounds__(416, 2)
k2_conv2(const float* __restrict__ w2, const float* __restrict__ b2) {
    extern __shared__ float sm2[];
    float* As  = sm2;           // 32 * 256 = 8192 floats (16x16 split-parity rows)
    float* w2s = sm2 + 8192;    // 9*32*64 = 18432
    float* b2s = w2s + 18432;   // 64

    const int b   = blockIdx.x;
    const int tid = threadIdx.x;

    for (int i = tid; i < 8192; i += 416) As[i] = 0.0f;
    for (int i = tid; i < 18432; i += 416) w2s[i] = w2[i];
    if (tid < 64) b2s[tid] = b2[tid];
    __syncthreads();

    const float* pin = g_p1 + (size_t)b * 6272;
    for (int i = tid; i < 6272; i += 416) {
        int ic = i / 196, r = i % 196;
        int y = r / 14, xx = r % 14;
        As[ic * 256 + (y + 1) * 16 + axm(xx + 1)] = pin[i];
    }
    __syncthreads();

    if (tid < 392) {
        const int ocg = tid / 49;
        const int p   = tid % 49;
        const int py  = p / 7, px = p % 7;

        unsigned long long acc[4][4];
#pragma unroll
        for (int i = 0; i < 4; i++)
#pragma unroll
            for (int j = 0; j < 4; j++) acc[i][j] = 0ULL;

#pragma unroll
        for (int ky = 0; ky < 3; ky++) {
#pragma unroll
            for (int kx = 0; kx < 3; kx++) {
                const int y  = 2 * py + ky;
                const int x0 = 2 * px + kx;
                const int o00 = y * 16 + axm(x0);
                const int o01 = y * 16 + axm(x0 + 1);
                const int o10 = o00 + 16;
                const int o11 = o01 + 16;
                const float* ap = As;
                const ulonglong2* wp = reinterpret_cast<const ulonglong2*>(
                    w2s + (ky * 3 + kx) * 32 * 64 + ocg * 8);
#pragma unroll 4
                for (int ic = 0; ic < 32; ic++) {
                    unsigned long long a00 = pack2(ap[o00]);
                    unsigned long long a01 = pack2(ap[o01]);
                    unsigned long long a10 = pack2(ap[o10]);
                    unsigned long long a11 = pack2(ap[o11]);
                    ulonglong2 w0  = wp[0];
                    ulonglong2 w1v = wp[1];
                    ffma2(acc[0][0], a00, w0.x);  ffma2(acc[0][1], a00, w0.y);
                    ffma2(acc[0][2], a00, w1v.x); ffma2(acc[0][3], a00, w1v.y);
                    ffma2(acc[1][0], a01, w0.x);  ffma2(acc[1][1], a01, w0.y);
                    ffma2(acc[1][2], a01, w1v.x); ffma2(acc[1][3], a01, w1v.y);
                    ffma2(acc[2][0], a10, w0.x);  ffma2(acc[2][1], a10, w0.y);
                    ffma2(acc[2][2], a10, w1v.x); ffma2(acc[2][3], a10, w1v.y);
                    ffma2(acc[3][0], a11, w0.x);  ffma2(acc[3][1], a11, w0.y);
                    ffma2(acc[3][2], a11, w1v.x); ffma2(acc[3][3], a11, w1v.y);
                    ap += 256;
                    wp += 16;
                }
            }
        }

        float* pout = g_p2 + (size_t)b * 64 * 49;
#pragma unroll
        for (int pr = 0; pr < 4; pr++) {
            int oc_lo = ocg * 8 + pr * 2;
            float blo = b2s[oc_lo], bhi = b2s[oc_lo + 1];
            float mlo = 0.0f, mhi = 0.0f;
#pragma unroll
            for (int pos = 0; pos < 4; pos++) {
                float lo, hi;
                unpack2(acc[pos][pr], lo, hi);
                mlo = fmaxf(mlo, fmaxf(lo + blo, 0.0f));
                mhi = fmaxf(mhi, fmaxf(hi + bhi, 0.0f));
            }
            pout[oc_lo * 49 + p]       = mlo;
            pout[(oc_lo + 1) * 49 + p] = mhi;
        }
    }
}

// ---------------------------------------------------------------------------
// K3a: conv3 (64->64, 3x3 SAME, relu) -> g_c3[b][3136] (NHWC)
// 2 images/CTA, 256 threads, w3 streamed as 9 double-buffered 16KB slabs.
// smem = 74.5KB -> occupancy 3 (24 warps/SM).
// ---------------------------------------------------------------------------
__global__ void __launch_bounds__(256, 3)
k3a_conv3(const float* __restrict__ w3, const float* __restrict__ b3) {
    extern __shared__ float sm3[];
    float* As   = sm3;            // 2 * 64 * 81 = 10368 (zero-padded acts)
    float* wbuf = As + 10368;     // 2 * 4096 double buffer
    float* b3s  = wbuf + 8192;    // 64
    // total 18624 floats = 74496 B

    const int tid = threadIdx.x;
    const int b0  = blockIdx.x * 2;

    for (int i = tid; i < 10368; i += 256) As[i] = 0.0f;
    if (tid < 64) b3s[tid] = b3[tid];
    __syncthreads();

#pragma unroll
    for (int img = 0; img < 2; img++) {
        const float* pin = g_p2 + (size_t)(b0 + img) * 3136;
        for (int i = tid; i < 3136; i += 256) {
            int ic = i / 49, r = i % 49;
            int y = r / 7, xx = r % 7;
            As[img * 5184 + ic * 81 + (y + 1) * 9 + xx + 1] = pin[i];
        }
    }

    // preload slab 0 (w3 slab s = contiguous 4096 floats for (ky,kx)=s)
    {
        const float4* src = reinterpret_cast<const float4*>(w3) + tid * 4;
        float4 r0 = src[0], r1 = src[1], r2 = src[2], r3 = src[3];
        float4* dst = reinterpret_cast<float4*>(wbuf) + tid * 4;
        dst[0] = r0; dst[1] = r1; dst[2] = r2; dst[3] = r3;
    }
    __syncthreads();

    // worker mapping: 224 workers = 2 img x 7 rows x 16 oc-groups (4 oc each)
    const int img = tid / 112;
    const int rr  = tid % 112;
    const int row = rr >> 4;
    const int ocg = rr & 15;
    const bool work = (tid < 224);

    unsigned long long acc[7][2];
#pragma unroll
    for (int i = 0; i < 7; i++) { acc[i][0] = 0ULL; acc[i][1] = 0ULL; }

    for (int s = 0; s < 9; s++) {
        float* wcur = wbuf + (s & 1) * 4096;

        // prefetch next slab into registers (overlaps with compute)
        float4 n0, n1, n2, n3;
        if (s < 8) {
            const float4* src = reinterpret_cast<const float4*>(w3 + (s + 1) * 4096)
                                + tid * 4;
            n0 = src[0]; n1 = src[1]; n2 = src[2]; n3 = src[3];
        }

        if (work) {
            const int ky = s / 3, kx = s % 3;
            const float* ap = As + img * 5184 + (row + ky) * 9 + kx;
            const ulonglong2* wp = reinterpret_cast<const ulonglong2*>(wcur) + ocg;
#pragma unroll 4
            for (int ic = 0; ic < 64; ic++) {
                ulonglong2 wv = wp[0];
                unsigned long long a[7];
#pragma unroll
                for (int xp = 0; xp < 7; xp++) a[xp] = pack2(ap[xp]);
#pragma unroll
                for (int xp = 0; xp < 7; xp++) {
                    ffma2(acc[xp][0], a[xp], wv.x);
                    ffma2(acc[xp][1], a[xp], wv.y);
                }
                ap += 81;
                wp += 16;   // 64 floats
            }
        }

        if (s < 8) {
            float4* dst = reinterpret_cast<float4*>(wbuf + ((s + 1) & 1) * 4096)
                          + tid * 4;
            dst[0] = n0; dst[1] = n1; dst[2] = n2; dst[3] = n3;
        }
        __syncthreads();
    }

    if (work) {
        const int oc0 = ocg * 4;
        float bb0 = b3s[oc0], bb1 = b3s[oc0 + 1], bb2 = b3s[oc0 + 2], bb3 = b3s[oc0 + 3];
        float* cb = g_c3 + (size_t)(b0 + img) * 3136;
#pragma unroll
        for (int xp = 0; xp < 7; xp++) {
            float v0, v1, v2, v3;
            unpack2(acc[xp][0], v0, v1);
            unpack2(acc[xp][1], v2, v3);
            float4 o;
            o.x = fmaxf(v0 + bb0, 0.0f);
            o.y = fmaxf(v1 + bb1, 0.0f);
            o.z = fmaxf(v2 + bb2, 0.0f);
            o.w = fmaxf(v3 + bb3, 0.0f);
            *reinterpret_cast<float4*>(cb + (row * 7 + xp) * 64 + oc0) = o;
        }
    }
}

// ---------------------------------------------------------------------------
// K3b: dense1 (3136->64, relu) as tiled GEMM + dense2(64->10) + softmax.
// M-tile = 16 batch rows, N = 64, K staged in 16 chunks of 196.
// 128 CTAs x 256 threads; thread = 1 batch x 4 oc (2 f32x2 acc).
// ---------------------------------------------------------------------------
__global__ void __launch_bounds__(256)
k3b_dense(const float* __restrict__ wd1, const float* __restrict__ bd1,
          const float* __restrict__ wd2, const float* __restrict__ bd2,
          float* __restrict__ out) {
    __shared__ float As[16 * 196];    // 12.25 KB
    __shared__ float Ws[196 * 64];    // 49 KB
    __shared__ float hs[16 * 64];

    const int tid = threadIdx.x;
    const int b0  = blockIdx.x * 16;
    const int bl  = tid >> 4;     // batch row 0..15 (slow within warp)
    const int ocq = tid & 15;     // oc group: oc = ocq*4

    unsigned long long acc0 = 0ULL, acc1 = 0ULL;

    for (int ch = 0; ch < 16; ch++) {
        // load A tile: 16 rows x 196 cols = 784 float4
        {
            const int k0 = ch * 196;
            for (int i = tid; i < 784; i += 256) {
                int r = i / 49, c4 = i % 49;
                reinterpret_cast<float4*>(As + r * 196)[c4] =
                    *reinterpret_cast<const float4*>(
                        g_c3 + (size_t)(b0 + r) * 3136 + k0 + c4 * 4);
            }
        }
        // load W tile: 196 x 64 = 3136 float4 (wd1 rows are contiguous)
        {
            const float4* src = reinterpret_cast<const float4*>(
                wd1 + (size_t)(ch * 196) * 64);
            for (int i = tid; i < 3136; i += 256)
                reinterpret_cast<float4*>(Ws)[i] = src[i];
        }
        __syncthreads();

        const float* arow = As + bl * 196;
#pragma unroll 4
        for (int k = 0; k < 196; k++) {
            unsigned long long a = pack2(arow[k]);
            ulonglong2 wv = reinterpret_cast<const ulonglong2*>(Ws + k * 64)[ocq];
            ffma2(acc0, a, wv.x);
            ffma2(acc1, a, wv.y);
        }
        __syncthreads();
    }

    // bias + relu -> hs
    {
        const int oc0 = ocq * 4;
        float v0, v1, v2, v3;
        unpack2(acc0, v0, v1);
        unpack2(acc1, v2, v3);
        float4 o;
        o.x = fmaxf(v0 + bd1[oc0],     0.0f);
        o.y = fmaxf(v1 + bd1[oc0 + 1], 0.0f);
        o.z = fmaxf(v2 + bd1[oc0 + 2], 0.0f);
        o.w = fmaxf(v3 + bd1[oc0 + 3], 0.0f);
        *reinterpret_cast<float4*>(hs + bl * 64 + oc0) = o;
    }
    __syncthreads();

    // dense2 + softmax: one thread per batch row
    if (tid < 16) {
        const float* h = hs + tid * 64;
        float lg[10];
#pragma unroll
        for (int c = 0; c < 10; c++) {
            float s = bd2[c];
#pragma unroll
            for (int j = 0; j < 64; j++)
                s = fmaf(h[j], wd2[j * 10 + c], s);
            lg[c] = s;
        }
        float m = lg[0];
#pragma unroll
        for (int c = 1; c < 10; c++) m = fmaxf(m, lg[c]);
        float se = 0.0f;
#pragma unroll
        for (int c = 0; c < 10; c++) { lg[c] = expf(lg[c] - m); se += lg[c]; }
        float inv = 1.0f / se;
        float* o = out + (size_t)(b0 + tid) * 10;
#pragma unroll
        for (int c = 0; c < 10; c++) o[c] = lg[c] * inv;
    }
}

// ---------------------------------------------------------------------------
extern "C" void kernel_launch(void* const* d_in, const int* in_sizes, int n_in,
                              void* d_out, int out_size) {
    const float* x   = (const float*)d_in[0];
    const float* w1  = (const float*)d_in[1];
    const float* b1  = (const float*)d_in[2];
    const float* w2  = (const float*)d_in[3];
    const float* b2  = (const float*)d_in[4];
    const float* w3  = (const float*)d_in[5];
    const float* b3  = (const float*)d_in[6];
    const float* wd1 = (const float*)d_in[7];
    const float* bd1 = (const float*)d_in[8];
    const float* wd2 = (const float*)d_in[9];
    const float* bd2 = (const float*)d_in[10];
    float* out = (float*)d_out;

    const int smem2  = (8192 + 18432 + 64) * 4;       // 106752
    const int smem3a = (10368 + 8192 + 64) * 4;       // 74496

    cudaFuncSetAttribute(k2_conv2,  cudaFuncAttributeMaxDynamicSharedMemorySize, smem2);
    cudaFuncSetAttribute(k3a_conv3, cudaFuncAttributeMaxDynamicSharedMemorySize, smem3a);

    k1_conv1<<<BATCH, 256>>>(x, w1, b1);
    k2_conv2<<<BATCH, 416, smem2>>>(w2, b2);
    k3a_conv3<<<BATCH / 2, 256, smem3a>>>(w3, b3);
    k3b_dense<<<BATCH / 16, 256>>>(wd1, bd1, wd2, bd2, out);
}

// round 7
// speedup vs baseline: 2.8443x; 2.1644x over previous
#include <cuda_runtime.h>
#include <math.h>
#include <stdint.h>

// ---------------------------------------------------------------------------
// Fused CNN, B=2048.
//  k0: w2 -> fragment-ordered tf32  k1: conv1+pool (fp32 scalar)
//  k2: conv2+pool via mma.sync tf32 (m16n8k8) implicit GEMM
//  k3a: conv3 (fp32 f32x2)          k3b: dense1+dense2+softmax
// ---------------------------------------------------------------------------

#define BATCH 2048

__device__ float g_p1[BATCH * 32 * 14 * 14];   // conv1+pool out, [b][ic][196]
__device__ float g_p2[BATCH * 64 * 7 * 7];     // conv2+pool out, [b][oc][49]
__device__ float g_c3[BATCH * 3136];           // conv3 out, NHWC-flattened
__device__ float g_w2f[9 * 4 * 8 * 32 * 2];    // w2 fragment-ordered, tf32

// ---------------- scalar helpers ----------------
__device__ __forceinline__ unsigned long long pack2(float x) {
    unsigned long long r;
    asm("mov.b64 %0, {%1, %1};" : "=l"(r) : "f"(x));
    return r;
}
__device__ __forceinline__ void ffma2(unsigned long long& d,
                                      unsigned long long a,
                                      unsigned long long b) {
    asm("fma.rn.f32x2 %0, %1, %2, %0;" : "+l"(d) : "l"(a), "l"(b));
}
__device__ __forceinline__ void unpack2(unsigned long long v, float& lo, float& hi) {
    asm("mov.b64 {%0, %1}, %2;" : "=f"(lo), "=f"(hi) : "l"(v));
}
__device__ __forceinline__ float tf32r(float v) {
    float o;
    asm("cvt.rna.tf32.f32 %0, %1;" : "=f"(o) : "f"(v));
    return o;
}
__device__ __forceinline__ uint32_t smem_u32(const void* p) {
    uint32_t a;
    asm("{ .reg .u64 t; cvta.to.shared.u64 t, %1; cvt.u32.u64 %0, t; }"
        : "=r"(a) : "l"(p));
    return a;
}
__device__ __forceinline__ uint32_t lds_u32(uint32_t a) {
    uint32_t v;
    asm volatile("ld.shared.b32 %0, [%1];" : "=r"(v) : "r"(a));
    return v;
}
__device__ __forceinline__ void lds_v2u(uint32_t a, uint32_t& x, uint32_t& y) {
    asm volatile("ld.shared.v2.b32 {%0,%1}, [%2];" : "=r"(x), "=r"(y) : "r"(a));
}
__device__ __forceinline__ float lds_f32(uint32_t a) {
    float v;
    asm volatile("ld.shared.f32 %0, [%1];" : "=f"(v) : "r"(a));
    return v;
}
__device__ __forceinline__ void sts_f32(uint32_t a, float v) {
    asm volatile("st.shared.f32 [%0], %1;" :: "r"(a), "f"(v));
}
__device__ __forceinline__ void sts_v4(uint32_t a, float4 v) {
    asm volatile("st.shared.v4.f32 [%0], {%1,%2,%3,%4};"
                 :: "r"(a), "f"(v.x), "f"(v.y), "f"(v.z), "f"(v.w));
}

__device__ __forceinline__ void mma16n8k8(float* d, uint32_t a0, uint32_t a1,
                                          uint32_t a2, uint32_t a3,
                                          uint32_t b0, uint32_t b1) {
    asm volatile(
        "mma.sync.aligned.m16n8k8.row.col.f32.tf32.tf32.f32 "
        "{%0,%1,%2,%3}, {%4,%5,%6,%7}, {%8,%9}, {%0,%1,%2,%3};"
        : "+f"(d[0]), "+f"(d[1]), "+f"(d[2]), "+f"(d[3])
        : "r"(a0), "r"(a1), "r"(a2), "r"(a3), "r"(b0), "r"(b1));
}

// ---------------------------------------------------------------------------
// K0: w2 [3][3][32][64] -> fragment-ordered tf32
// g_w2f[((tap*4+ks)*8+nt)*64 + lane*2 + j] = w2[tap][ks*8 + t + 4j][nt*8 + g]
// (lane = 4g+t;  t = lane&3, g = lane>>2)
// ---------------------------------------------------------------------------
__global__ void k0_prep(const float* __restrict__ w2) {
    int i = blockIdx.x * 256 + threadIdx.x;
    if (i < 18432) {
        int j    = i & 1;
        int lane = (i >> 1) & 31;
        int nt   = (i >> 6) & 7;
        int ks   = (i >> 9) & 3;
        int tap  = i >> 11;
        int t = lane & 3, g = lane >> 2;
        int ic = ks * 8 + t + 4 * j;
        int oc = nt * 8 + g;
        g_w2f[i] = tf32r(w2[tap * 2048 + ic * 64 + oc]);
    }
}

// ---------------------------------------------------------------------------
// K1: conv1 (1->32, 3x3 SAME) + relu + maxpool2 -> g_p1
// ---------------------------------------------------------------------------
__global__ void __launch_bounds__(256)
k1_conv1(const float* __restrict__ x, const float* __restrict__ w1,
         const float* __restrict__ b1) {
    __shared__ float xs[30 * 30];
    __shared__ float w1s[9 * 32];
    __shared__ float b1s[32];

    const int b   = blockIdx.x;
    const int tid = threadIdx.x;

    for (int i = tid; i < 900; i += 256) xs[i] = 0.0f;
    for (int i = tid; i < 288; i += 256) w1s[i] = w1[i];
    if (tid < 32) b1s[tid] = b1[tid];
    __syncthreads();

    const float* xb = x + b * 784;
    for (int i = tid; i < 784; i += 256) {
        int y = i / 28, xx = i % 28;
        xs[(y + 1) * 30 + xx + 1] = xb[i];
    }
    __syncthreads();

    const int oc0  = tid >> 5;
    const int lane = tid & 31;
    float* pb = g_p1 + (size_t)b * 32 * 196;

    for (int oc = oc0; oc < 32; oc += 8) {
        float wk[9];
#pragma unroll
        for (int t = 0; t < 9; t++) wk[t] = w1s[t * 32 + oc];
        const float bias = b1s[oc];

        for (int p = lane; p < 196; p += 32) {
            int py = p / 14, px = p % 14;
            float m = 0.0f;
#pragma unroll
            for (int dy = 0; dy < 2; dy++) {
#pragma unroll
                for (int dx = 0; dx < 2; dx++) {
                    int y = 2 * py + dy, xx = 2 * px + dx;
                    float s = bias;
#pragma unroll
                    for (int ky = 0; ky < 3; ky++)
#pragma unroll
                        for (int kx = 0; kx < 3; kx++)
                            s = fmaf(xs[(y + ky) * 30 + xx + kx], wk[ky * 3 + kx], s);
                    m = fmaxf(m, fmaxf(s, 0.0f));
                }
            }
            pb[oc * 196 + p] = m;
        }
    }
}

// ---------------------------------------------------------------------------
// K2: conv2 via mma.sync tf32. One image per CTA, 256 threads (8 warps).
// GEMM: [224(196 valid) x 288] x [288 x 64], K = 9 taps x 32 ic.
// Apad[256 pos][pitch 36] (conflict-free A-frag loads), tap = addr shift.
// B fragment-ordered in smem (1 conflict-free LDS.64 per frag).
// Epilogue: frags -> Csm (pitch 65, aliases Apad/Wf; SCALAR stores — v2
// would be 8B-misaligned on odd rows) + bias + relu, then 2x2 maxpool.
// ---------------------------------------------------------------------------
#define K2_AP_BYTES  36864u            // 256*36*4
#define K2_WF_BYTES  73728u            // 18432*4
#define K2_BS_OFF    (K2_AP_BYTES + K2_WF_BYTES)    // 110592
#define K2_SMEM      (K2_BS_OFF + 256)              // 110848

__global__ void __launch_bounds__(256, 2)
k2_conv2_mma(const float* __restrict__ b2) {
    extern __shared__ float sm[];
    const uint32_t S0 = smem_u32(sm);
    const uint32_t A0 = S0;
    const uint32_t W0 = S0 + K2_AP_BYTES;
    const uint32_t BS = S0 + K2_BS_OFF;
    const uint32_t C0 = S0;            // epilogue alias

    const int tid = threadIdx.x;
    const int b   = blockIdx.x;
    const int wid = tid >> 5;
    const int ln  = tid & 31;
    const int t   = ln & 3;
    const int g   = ln >> 2;

    // zero Apad
    float4 z4 = make_float4(0.f, 0.f, 0.f, 0.f);
    for (int u = tid; u < 2304; u += 256) sts_v4(A0 + u * 16, z4);
    // copy fragment-ordered weights
    {
        const float4* src = (const float4*)g_w2f;
        for (int u = tid; u < 4608; u += 256) {
            float4 v = src[u];
            sts_v4(W0 + u * 16, v);
        }
    }
    if (tid < 64) sts_f32(BS + tid * 4, b2[tid]);
    __syncthreads();

    // fill Apad: act(y,x,ic) -> pos=(y+1)*16+(x+1), tf32
    const float* pin = g_p1 + (size_t)b * 6272;
    for (int i = tid; i < 6272; i += 256) {
        int ic = i / 196, p = i % 196;
        int y = p / 14, xx = p % 14;
        uint32_t addr = A0 + (uint32_t)(((y + 1) * 16 + xx + 1) * 144 + ic * 4);
        sts_f32(addr, tf32r(pin[i]));
    }
    __syncthreads();

    // per-lane A base addresses (2 m-tiles, rows g and g+8 each)
    uint32_t bA[2][2];
#pragma unroll
    for (int mt = 0; mt < 2; mt++) {
        int r0 = (wid * 2 + mt) * 16 + g;
        int p0 = min(r0, 195);
        int p1 = min(r0 + 8, 195);
        bA[mt][0] = A0 + (uint32_t)(((p0 / 14) * 16 + p0 % 14) * 144 + t * 4);
        bA[mt][1] = A0 + (uint32_t)(((p1 / 14) * 16 + p1 % 14) * 144 + t * 4);
    }
    const uint32_t wfl = W0 + ln * 8;

    float acc[2][8][4];
#pragma unroll
    for (int mt = 0; mt < 2; mt++)
#pragma unroll
        for (int nt = 0; nt < 8; nt++)
#pragma unroll
            for (int j = 0; j < 4; j++) acc[mt][nt][j] = 0.0f;

    for (int tap = 0; tap < 9; tap++) {
        const uint32_t toff = (uint32_t)(((tap / 3) * 16 + tap % 3) * 144);
        const uint32_t wtap = wfl + (uint32_t)(tap * 8192);   // 4 ks * 8 nt * 256B
#pragma unroll
        for (int ks = 0; ks < 4; ks++) {
            uint32_t a[2][4];
#pragma unroll
            for (int mt = 0; mt < 2; mt++) {
                uint32_t c0 = bA[mt][0] + toff + ks * 32;
                uint32_t c1 = bA[mt][1] + toff + ks * 32;
                a[mt][0] = lds_u32(c0);
                a[mt][1] = lds_u32(c1);
                a[mt][2] = lds_u32(c0 + 16);
                a[mt][3] = lds_u32(c1 + 16);
            }
            const uint32_t wks = wtap + ks * 2048;
#pragma unroll
            for (int nt = 0; nt < 8; nt++) {
                uint32_t b0, b1;
                lds_v2u(wks + nt * 256, b0, b1);
                mma16n8k8(acc[0][nt], a[0][0], a[0][1], a[0][2], a[0][3], b0, b1);
                mma16n8k8(acc[1][nt], a[1][0], a[1][1], a[1][2], a[1][3], b0, b1);
            }
        }
    }

    // bias (read before alias overwrite; BS not aliased)
    float bs0[8], bs1[8];
#pragma unroll
    for (int nt = 0; nt < 8; nt++) {
        bs0[nt] = lds_f32(BS + (nt * 8 + 2 * t) * 4);
        bs1[nt] = lds_f32(BS + (nt * 8 + 2 * t + 1) * 4);
    }
    __syncthreads();   // everyone done with Apad/Wf

    // write conv output (relu) to Csm[p][oc], pitch 65 — scalar stores
#pragma unroll
    for (int mt = 0; mt < 2; mt++) {
        int r0 = (wid * 2 + mt) * 16 + g;
        int r1 = r0 + 8;
#pragma unroll
        for (int nt = 0; nt < 8; nt++) {
            int c = nt * 8 + 2 * t;
            if (r0 < 196) {
                uint32_t ad = C0 + (uint32_t)((r0 * 65 + c) * 4);
                sts_f32(ad,     fmaxf(acc[mt][nt][0] + bs0[nt], 0.0f));
                sts_f32(ad + 4, fmaxf(acc[mt][nt][1] + bs1[nt], 0.0f));
            }
            if (r1 < 196) {
                uint32_t ad = C0 + (uint32_t)((r1 * 65 + c) * 4);
                sts_f32(ad,     fmaxf(acc[mt][nt][2] + bs0[nt], 0.0f));
                sts_f32(ad + 4, fmaxf(acc[mt][nt][3] + bs1[nt], 0.0f));
            }
        }
    }
    __syncthreads();

    // 2x2 maxpool -> g_p2[b][oc][49], coalesced
    float* pout = g_p2 + (size_t)b * 3136;
    for (int i = tid; i < 3136; i += 256) {
        int oc = i / 49, pp = i % 49;
        int py = pp / 7, px = pp % 7;
        int p00 = (2 * py) * 14 + 2 * px;
        float v0 = lds_f32(C0 + (uint32_t)((p00 * 65 + oc) * 4));
        float v1 = lds_f32(C0 + (uint32_t)(((p00 + 1) * 65 + oc) * 4));
        float v2 = lds_f32(C0 + (uint32_t)(((p00 + 14) * 65 + oc) * 4));
        float v3 = lds_f32(C0 + (uint32_t)(((p00 + 15) * 65 + oc) * 4));
        pout[i] = fmaxf(fmaxf(v0, v1), fmaxf(v2, v3));
    }
}

// ---------------------------------------------------------------------------
// K3a: conv3 (64->64, 3x3 SAME, relu) -> g_c3 (NHWC). (R3, unchanged)
// ---------------------------------------------------------------------------
__global__ void __launch_bounds__(256, 3)
k3a_conv3(const float* __restrict__ w3, const float* __restrict__ b3) {
    extern __shared__ float sm3[];
    float* As   = sm3;            // 2 * 64 * 81
    float* wbuf = As + 10368;     // 2 * 4096
    float* b3s  = wbuf + 8192;    // 64

    const int tid = threadIdx.x;
    const int b0  = blockIdx.x * 2;

    for (int i = tid; i < 10368; i += 256) As[i] = 0.0f;
    if (tid < 64) b3s[tid] = b3[tid];
    __syncthreads();

#pragma unroll
    for (int img = 0; img < 2; img++) {
        const float* pin = g_p2 + (size_t)(b0 + img) * 3136;
        for (int i = tid; i < 3136; i += 256) {
            int ic = i / 49, r = i % 49;
            int y = r / 7, xx = r % 7;
            As[img * 5184 + ic * 81 + (y + 1) * 9 + xx + 1] = pin[i];
        }
    }
    {
        const float4* src = reinterpret_cast<const float4*>(w3) + tid * 4;
        float4 r0 = src[0], r1 = src[1], r2 = src[2], r3 = src[3];
        float4* dst = reinterpret_cast<float4*>(wbuf) + tid * 4;
        dst[0] = r0; dst[1] = r1; dst[2] = r2; dst[3] = r3;
    }
    __syncthreads();

    const int img = tid / 112;
    const int rr  = tid % 112;
    const int row = rr >> 4;
    const int ocg = rr & 15;
    const bool work = (tid < 224);

    unsigned long long acc[7][2];
#pragma unroll
    for (int i = 0; i < 7; i++) { acc[i][0] = 0ULL; acc[i][1] = 0ULL; }

    for (int s = 0; s < 9; s++) {
        float* wcur = wbuf + (s & 1) * 4096;
        float4 n0, n1, n2, n3;
        if (s < 8) {
            const float4* src = reinterpret_cast<const float4*>(w3 + (s + 1) * 4096)
                                + tid * 4;
            n0 = src[0]; n1 = src[1]; n2 = src[2]; n3 = src[3];
        }
        if (work) {
            const int ky = s / 3, kx = s % 3;
            const float* ap = As + img * 5184 + (row + ky) * 9 + kx;
            const ulonglong2* wp = reinterpret_cast<const ulonglong2*>(wcur) + ocg;
#pragma unroll 4
            for (int ic = 0; ic < 64; ic++) {
                ulonglong2 wv = wp[0];
                unsigned long long a[7];
#pragma unroll
                for (int xp = 0; xp < 7; xp++) a[xp] = pack2(ap[xp]);
#pragma unroll
                for (int xp = 0; xp < 7; xp++) {
                    ffma2(acc[xp][0], a[xp], wv.x);
                    ffma2(acc[xp][1], a[xp], wv.y);
                }
                ap += 81;
                wp += 16;
            }
        }
        if (s < 8) {
            float4* dst = reinterpret_cast<float4*>(wbuf + ((s + 1) & 1) * 4096)
                          + tid * 4;
            dst[0] = n0; dst[1] = n1; dst[2] = n2; dst[3] = n3;
        }
        __syncthreads();
    }

    if (work) {
        const int oc0 = ocg * 4;
        float bb0 = b3s[oc0], bb1 = b3s[oc0 + 1], bb2 = b3s[oc0 + 2], bb3 = b3s[oc0 + 3];
        float* cb = g_c3 + (size_t)(b0 + img) * 3136;
#pragma unroll
        for (int xp = 0; xp < 7; xp++) {
            float v0, v1, v2, v3;
            unpack2(acc[xp][0], v0, v1);
            unpack2(acc[xp][1], v2, v3);
            float4 o;
            o.x = fmaxf(v0 + bb0, 0.0f);
            o.y = fmaxf(v1 + bb1, 0.0f);
            o.z = fmaxf(v2 + bb2, 0.0f);
            o.w = fmaxf(v3 + bb3, 0.0f);
            *reinterpret_cast<float4*>(cb + (row * 7 + xp) * 64 + oc0) = o;
        }
    }
}

// ---------------------------------------------------------------------------
// K3b: dense1 (3136->64, relu) + dense2(64->10) + softmax.
// M=8 rows/CTA, 256 CTAs, 2 oc/thread.
// ---------------------------------------------------------------------------
__global__ void __launch_bounds__(256)
k3b_dense(const float* __restrict__ wd1, const float* __restrict__ bd1,
          const float* __restrict__ wd2, const float* __restrict__ bd2,
          float* __restrict__ out) {
    __shared__ float As[8 * 196];
    __shared__ float Ws[196 * 64];
    __shared__ float hs[8 * 64];

    const int tid = threadIdx.x;
    const int b0  = blockIdx.x * 8;
    const int bl  = tid >> 5;      // 0..7
    const int ocp = tid & 31;      // oc-pair index

    unsigned long long acc0 = 0ULL, acc1 = 0ULL;

    for (int ch = 0; ch < 16; ch++) {
        for (int i = tid; i < 392; i += 256) {
            int r = i / 49, c = i % 49;
            reinterpret_cast<float4*>(As + r * 196)[c] =
                *reinterpret_cast<const float4*>(
                    g_c3 + (size_t)(b0 + r) * 3136 + ch * 196 + c * 4);
        }
        const float4* src = reinterpret_cast<const float4*>(
            wd1 + (size_t)(ch * 196) * 64);
        for (int i = tid; i < 3136; i += 256)
            reinterpret_cast<float4*>(Ws)[i] = src[i];
        __syncthreads();

        const float* arow = As + bl * 196;
        const unsigned long long* wp =
            reinterpret_cast<const unsigned long long*>(Ws) + ocp;
#pragma unroll 2
        for (int k = 0; k < 196; k += 2) {
            ffma2(acc0, pack2(arow[k]),     wp[(size_t)k * 32]);
            ffma2(acc1, pack2(arow[k + 1]), wp[(size_t)(k + 1) * 32]);
        }
        __syncthreads();
    }

    {
        float v0, v1, u0, u1;
        unpack2(acc0, v0, v1);
        unpack2(acc1, u0, u1);
        int oc0 = ocp * 2;
        hs[bl * 64 + oc0]     = fmaxf(v0 + u0 + bd1[oc0],     0.0f);
        hs[bl * 64 + oc0 + 1] = fmaxf(v1 + u1 + bd1[oc0 + 1], 0.0f);
    }
    __syncthreads();

    if (tid < 8) {
        const float* h = hs + tid * 64;
        float lg[10];
#pragma unroll
        for (int c = 0; c < 10; c++) {
            float s = bd2[c];
#pragma unroll
            for (int j = 0; j < 64; j++)
                s = fmaf(h[j], wd2[j * 10 + c], s);
            lg[c] = s;
        }
        float m = lg[0];
#pragma unroll
        for (int c = 1; c < 10; c++) m = fmaxf(m, lg[c]);
        float se = 0.0f;
#pragma unroll
        for (int c = 0; c < 10; c++) { lg[c] = expf(lg[c] - m); se += lg[c]; }
        float inv = 1.0f / se;
        float* o = out + (size_t)(b0 + tid) * 10;
#pragma unroll
        for (int c = 0; c < 10; c++) o[c] = lg[c] * inv;
    }
}

// ---------------------------------------------------------------------------
extern "C" void kernel_launch(void* const* d_in, const int* in_sizes, int n_in,
                              void* d_out, int out_size) {
    const float* x   = (const float*)d_in[0];
    const float* w1  = (const float*)d_in[1];
    const float* b1  = (const float*)d_in[2];
    const float* w2  = (const float*)d_in[3];
    const float* b2  = (const float*)d_in[4];
    const float* w3  = (const float*)d_in[5];
    const float* b3  = (const float*)d_in[6];
    const float* wd1 = (const float*)d_in[7];
    const float* bd1 = (const float*)d_in[8];
    const float* wd2 = (const float*)d_in[9];
    const float* bd2 = (const float*)d_in[10];
    float* out = (float*)d_out;

    const int smem3a = (10368 + 8192 + 64) * 4;   // 74496

    cudaFuncSetAttribute(k2_conv2_mma, cudaFuncAttributeMaxDynamicSharedMemorySize, K2_SMEM);
    cudaFuncSetAttribute(k3a_conv3,    cudaFuncAttributeMaxDynamicSharedMemorySize, smem3a);

    k0_prep<<<72, 256>>>(w2);
    k1_conv1<<<BATCH, 256>>>(x, w1, b1);
    k2_conv2_mma<<<BATCH, 256, K2_SMEM>>>(b2);
    k3a_conv3<<<BATCH / 2, 256, smem3a>>>(w3, b3);
    k3b_dense<<<BATCH / 8, 256>>>(wd1, bd1, wd2, bd2, out);
}

// round 8
// speedup vs baseline: 3.8309x; 1.3469x over previous
#include <cuda_runtime.h>
#include <math.h>
#include <stdint.h>

// ---------------------------------------------------------------------------
// Fused CNN, B=2048.
//  k0: w2,w3 -> fragment-ordered tf32   k1: conv1+pool (fp32 scalar)
//  k2: conv2+pool via mma.sync tf32     k3a: conv3 via mma.sync tf32
//  k3b: dense1+dense2+softmax (fp32)
// ---------------------------------------------------------------------------

#define BATCH 2048

__device__ float g_p1[BATCH * 32 * 14 * 14];   // conv1+pool out, [b][ic][196]
__device__ float g_p2[BATCH * 64 * 7 * 7];     // conv2+pool out, [b][oc][49]
__device__ float g_c3[BATCH * 3136];           // conv3 out, NHWC-flattened
__device__ float g_w2f[9 * 4 * 8 * 32 * 2];    // w2 fragment-ordered, tf32
__device__ float g_w3f[9 * 8 * 8 * 32 * 2];    // w3 fragment-ordered, tf32

// ---------------- scalar helpers ----------------
__device__ __forceinline__ unsigned long long pack2(float x) {
    unsigned long long r;
    asm("mov.b64 %0, {%1, %1};" : "=l"(r) : "f"(x));
    return r;
}
__device__ __forceinline__ void ffma2(unsigned long long& d,
                                      unsigned long long a,
                                      unsigned long long b) {
    asm("fma.rn.f32x2 %0, %1, %2, %0;" : "+l"(d) : "l"(a), "l"(b));
}
__device__ __forceinline__ void unpack2(unsigned long long v, float& lo, float& hi) {
    asm("mov.b64 {%0, %1}, %2;" : "=f"(lo), "=f"(hi) : "l"(v));
}
__device__ __forceinline__ float tf32r(float v) {
    float o;
    asm("cvt.rna.tf32.f32 %0, %1;" : "=f"(o) : "f"(v));
    return o;
}
__device__ __forceinline__ uint32_t smem_u32(const void* p) {
    uint32_t a;
    asm("{ .reg .u64 t; cvta.to.shared.u64 t, %1; cvt.u32.u64 %0, t; }"
        : "=r"(a) : "l"(p));
    return a;
}
__device__ __forceinline__ uint32_t lds_u32(uint32_t a) {
    uint32_t v;
    asm volatile("ld.shared.b32 %0, [%1];" : "=r"(v) : "r"(a));
    return v;
}
__device__ __forceinline__ void lds_v2u(uint32_t a, uint32_t& x, uint32_t& y) {
    asm volatile("ld.shared.v2.b32 {%0,%1}, [%2];" : "=r"(x), "=r"(y) : "r"(a));
}
__device__ __forceinline__ float lds_f32(uint32_t a) {
    float v;
    asm volatile("ld.shared.f32 %0, [%1];" : "=f"(v) : "r"(a));
    return v;
}
__device__ __forceinline__ void sts_f32(uint32_t a, float v) {
    asm volatile("st.shared.f32 [%0], %1;" :: "r"(a), "f"(v));
}
__device__ __forceinline__ void sts_v4(uint32_t a, float4 v) {
    asm volatile("st.shared.v4.f32 [%0], {%1,%2,%3,%4};"
                 :: "r"(a), "f"(v.x), "f"(v.y), "f"(v.z), "f"(v.w));
}

__device__ __forceinline__ void mma16n8k8(float* d, uint32_t a0, uint32_t a1,
                                          uint32_t a2, uint32_t a3,
                                          uint32_t b0, uint32_t b1) {
    asm volatile(
        "mma.sync.aligned.m16n8k8.row.col.f32.tf32.tf32.f32 "
        "{%0,%1,%2,%3}, {%4,%5,%6,%7}, {%8,%9}, {%0,%1,%2,%3};"
        : "+f"(d[0]), "+f"(d[1]), "+f"(d[2]), "+f"(d[3])
        : "r"(a0), "r"(a1), "r"(a2), "r"(a3), "r"(b0), "r"(b1));
}

// ---------------------------------------------------------------------------
// K0: w2 [3][3][32][64] and w3 [3][3][64][64] -> fragment-ordered tf32
// g_wXf[((tap*KS+ks)*8+nt)*64 + lane*2 + j] = wX[tap][ks*8 + t + 4j][nt*8 + g]
// ---------------------------------------------------------------------------
__global__ void k0_prep(const float* __restrict__ w2, const float* __restrict__ w3) {
    int i = blockIdx.x * 256 + threadIdx.x;
    if (i < 18432) {
        int j    = i & 1;
        int lane = (i >> 1) & 31;
        int nt   = (i >> 6) & 7;
        int ks   = (i >> 9) & 3;
        int tap  = i >> 11;
        int t = lane & 3, g = lane >> 2;
        int ic = ks * 8 + t + 4 * j;
        int oc = nt * 8 + g;
        g_w2f[i] = tf32r(w2[tap * 2048 + ic * 64 + oc]);
    } else if (i < 55296) {
        int k    = i - 18432;
        int j    = k & 1;
        int lane = (k >> 1) & 31;
        int nt   = (k >> 6) & 7;
        int ks   = (k >> 9) & 7;
        int tap  = k >> 12;
        int t = lane & 3, g = lane >> 2;
        int ic = ks * 8 + t + 4 * j;
        int oc = nt * 8 + g;
        g_w3f[k] = tf32r(w3[tap * 4096 + ic * 64 + oc]);
    }
}

// ---------------------------------------------------------------------------
// K1: conv1 (1->32, 3x3 SAME) + relu + maxpool2 -> g_p1
// ---------------------------------------------------------------------------
__global__ void __launch_bounds__(256)
k1_conv1(const float* __restrict__ x, const float* __restrict__ w1,
         const float* __restrict__ b1) {
    __shared__ float xs[30 * 30];
    __shared__ float w1s[9 * 32];
    __shared__ float b1s[32];

    const int b   = blockIdx.x;
    const int tid = threadIdx.x;

    for (int i = tid; i < 900; i += 256) xs[i] = 0.0f;
    for (int i = tid; i < 288; i += 256) w1s[i] = w1[i];
    if (tid < 32) b1s[tid] = b1[tid];
    __syncthreads();

    const float* xb = x + b * 784;
    for (int i = tid; i < 784; i += 256) {
        int y = i / 28, xx = i % 28;
        xs[(y + 1) * 30 + xx + 1] = xb[i];
    }
    __syncthreads();

    const int oc0  = tid >> 5;
    const int lane = tid & 31;
    float* pb = g_p1 + (size_t)b * 32 * 196;

    for (int oc = oc0; oc < 32; oc += 8) {
        float wk[9];
#pragma unroll
        for (int t = 0; t < 9; t++) wk[t] = w1s[t * 32 + oc];
        const float bias = b1s[oc];

        for (int p = lane; p < 196; p += 32) {
            int py = p / 14, px = p % 14;
            float m = 0.0f;
#pragma unroll
            for (int dy = 0; dy < 2; dy++) {
#pragma unroll
                for (int dx = 0; dx < 2; dx++) {
                    int y = 2 * py + dy, xx = 2 * px + dx;
                    float s = bias;
#pragma unroll
                    for (int ky = 0; ky < 3; ky++)
#pragma unroll
                        for (int kx = 0; kx < 3; kx++)
                            s = fmaf(xs[(y + ky) * 30 + xx + kx], wk[ky * 3 + kx], s);
                    m = fmaxf(m, fmaxf(s, 0.0f));
                }
            }
            pb[oc * 196 + p] = m;
        }
    }
}

// ---------------------------------------------------------------------------
// K2: conv2 via mma.sync tf32 (unchanged from R7 pass).
// ---------------------------------------------------------------------------
#define K2_AP_BYTES  36864u
#define K2_WF_BYTES  73728u
#define K2_BS_OFF    (K2_AP_BYTES + K2_WF_BYTES)
#define K2_SMEM      (K2_BS_OFF + 256)

__global__ void __launch_bounds__(256, 2)
k2_conv2_mma(const float* __restrict__ b2) {
    extern __shared__ float sm[];
    const uint32_t S0 = smem_u32(sm);
    const uint32_t A0 = S0;
    const uint32_t W0 = S0 + K2_AP_BYTES;
    const uint32_t BS = S0 + K2_BS_OFF;
    const uint32_t C0 = S0;            // epilogue alias

    const int tid = threadIdx.x;
    const int b   = blockIdx.x;
    const int wid = tid >> 5;
    const int ln  = tid & 31;
    const int t   = ln & 3;
    const int g   = ln >> 2;

    float4 z4 = make_float4(0.f, 0.f, 0.f, 0.f);
    for (int u = tid; u < 2304; u += 256) sts_v4(A0 + u * 16, z4);
    {
        const float4* src = (const float4*)g_w2f;
        for (int u = tid; u < 4608; u += 256) {
            float4 v = src[u];
            sts_v4(W0 + u * 16, v);
        }
    }
    if (tid < 64) sts_f32(BS + tid * 4, b2[tid]);
    __syncthreads();

    const float* pin = g_p1 + (size_t)b * 6272;
    for (int i = tid; i < 6272; i += 256) {
        int ic = i / 196, p = i % 196;
        int y = p / 14, xx = p % 14;
        uint32_t addr = A0 + (uint32_t)(((y + 1) * 16 + xx + 1) * 144 + ic * 4);
        sts_f32(addr, tf32r(pin[i]));
    }
    __syncthreads();

    uint32_t bA[2][2];
#pragma unroll
    for (int mt = 0; mt < 2; mt++) {
        int r0 = (wid * 2 + mt) * 16 + g;
        int p0 = min(r0, 195);
        int p1 = min(r0 + 8, 195);
        bA[mt][0] = A0 + (uint32_t)(((p0 / 14) * 16 + p0 % 14) * 144 + t * 4);
        bA[mt][1] = A0 + (uint32_t)(((p1 / 14) * 16 + p1 % 14) * 144 + t * 4);
    }
    const uint32_t wfl = W0 + ln * 8;

    float acc[2][8][4];
#pragma unroll
    for (int mt = 0; mt < 2; mt++)
#pragma unroll
        for (int nt = 0; nt < 8; nt++)
#pragma unroll
            for (int j = 0; j < 4; j++) acc[mt][nt][j] = 0.0f;

    for (int tap = 0; tap < 9; tap++) {
        const uint32_t toff = (uint32_t)(((tap / 3) * 16 + tap % 3) * 144);
        const uint32_t wtap = wfl + (uint32_t)(tap * 8192);
#pragma unroll
        for (int ks = 0; ks < 4; ks++) {
            uint32_t a[2][4];
#pragma unroll
            for (int mt = 0; mt < 2; mt++) {
                uint32_t c0 = bA[mt][0] + toff + ks * 32;
                uint32_t c1 = bA[mt][1] + toff + ks * 32;
                a[mt][0] = lds_u32(c0);
                a[mt][1] = lds_u32(c1);
                a[mt][2] = lds_u32(c0 + 16);
                a[mt][3] = lds_u32(c1 + 16);
            }
            const uint32_t wks = wtap + ks * 2048;
#pragma unroll
            for (int nt = 0; nt < 8; nt++) {
                uint32_t b0, b1;
                lds_v2u(wks + nt * 256, b0, b1);
                mma16n8k8(acc[0][nt], a[0][0], a[0][1], a[0][2], a[0][3], b0, b1);
                mma16n8k8(acc[1][nt], a[1][0], a[1][1], a[1][2], a[1][3], b0, b1);
            }
        }
    }

    float bs0[8], bs1[8];
#pragma unroll
    for (int nt = 0; nt < 8; nt++) {
        bs0[nt] = lds_f32(BS + (nt * 8 + 2 * t) * 4);
        bs1[nt] = lds_f32(BS + (nt * 8 + 2 * t + 1) * 4);
    }
    __syncthreads();

#pragma unroll
    for (int mt = 0; mt < 2; mt++) {
        int r0 = (wid * 2 + mt) * 16 + g;
        int r1 = r0 + 8;
#pragma unroll
        for (int nt = 0; nt < 8; nt++) {
            int c = nt * 8 + 2 * t;
            if (r0 < 196) {
                uint32_t ad = C0 + (uint32_t)((r0 * 65 + c) * 4);
                sts_f32(ad,     fmaxf(acc[mt][nt][0] + bs0[nt], 0.0f));
                sts_f32(ad + 4, fmaxf(acc[mt][nt][1] + bs1[nt], 0.0f));
            }
            if (r1 < 196) {
                uint32_t ad = C0 + (uint32_t)((r1 * 65 + c) * 4);
                sts_f32(ad,     fmaxf(acc[mt][nt][2] + bs0[nt], 0.0f));
                sts_f32(ad + 4, fmaxf(acc[mt][nt][3] + bs1[nt], 0.0f));
            }
        }
    }
    __syncthreads();

    float* pout = g_p2 + (size_t)b * 3136;
    for (int i = tid; i < 3136; i += 256) {
        int oc = i / 49, pp = i % 49;
        int py = pp / 7, px = pp % 7;
        int p00 = (2 * py) * 14 + 2 * px;
        float v0 = lds_f32(C0 + (uint32_t)((p00 * 65 + oc) * 4));
        float v1 = lds_f32(C0 + (uint32_t)(((p00 + 1) * 65 + oc) * 4));
        float v2 = lds_f32(C0 + (uint32_t)(((p00 + 14) * 65 + oc) * 4));
        float v3 = lds_f32(C0 + (uint32_t)(((p00 + 15) * 65 + oc) * 4));
        pout[i] = fmaxf(fmaxf(v0, v1), fmaxf(v2, v3));
    }
}

// ---------------------------------------------------------------------------
// K3a: conv3 via mma.sync tf32. 4 images/CTA, 256 threads (8 warps).
// A: [4 img][81 raster pos][pitch 68 ic] tf32, zero-padded; tap = addr shift
// (ky*9+kx)*pitch.  Weights streamed per-tap (16KB slabs, double-buffered).
// Warp = 1 image half: 2 m16 tiles x 8 n8 tiles; K = 9 taps x 8 k8-steps.
// Epilogue: c-frag -> bias+relu -> st.global.v2 to g_c3 NHWC (direct).
// ---------------------------------------------------------------------------
#define K3_A_BYTES   88128u                       // 4*81*68*4
#define K3_W_OFF     K3_A_BYTES                   // 2 * 16384
#define K3_BS_OFF    (K3_A_BYTES + 32768u)        // 120896
#define K3_SMEM      (K3_BS_OFF + 256u)           // 121152

__global__ void __launch_bounds__(256, 1)
k3a_conv3_mma(const float* __restrict__ b3) {
    extern __shared__ float sm3[];
    const uint32_t S0 = smem_u32(sm3);
    const uint32_t A0 = S0;
    const uint32_t W0 = S0 + K3_W_OFF;
    const uint32_t BS = S0 + K3_BS_OFF;

    const int tid = threadIdx.x;
    const int b0  = blockIdx.x * 4;
    const int wid = tid >> 5;
    const int ln  = tid & 31;
    const int t   = ln & 3;
    const int g   = ln >> 2;

    // zero A (22032 floats = 5508 float4)
    float4 z4 = make_float4(0.f, 0.f, 0.f, 0.f);
    for (int u = tid; u < 5508; u += 256) sts_v4(A0 + u * 16, z4);
    if (tid < 64) sts_f32(BS + tid * 4, b3[tid]);
    __syncthreads();

    // fill A: g_p2[b][ic][49] -> A[img][(y+1)*9+(x+1)][ic], tf32
#pragma unroll
    for (int img = 0; img < 4; img++) {
        const float* pin = g_p2 + (size_t)(b0 + img) * 3136;
        for (int i = tid; i < 3136; i += 256) {
            int ic = i / 49, p = i % 49;
            int y = p / 7, xx = p % 7;
            uint32_t addr = A0 +
                (uint32_t)((img * 5508 + ((y + 1) * 9 + xx + 1) * 68 + ic) * 4);
            sts_f32(addr, tf32r(pin[i]));
        }
    }

    // preload tap-0 weight slab (4096 floats = 1024 float4)
    {
        const float4* src = (const float4*)g_w3f + tid * 4;
        float4 r0 = src[0], r1 = src[1], r2 = src[2], r3 = src[3];
        uint32_t dst = W0 + tid * 64;
        sts_v4(dst,      r0); sts_v4(dst + 16, r1);
        sts_v4(dst + 32, r2); sts_v4(dst + 48, r3);
    }
    __syncthreads();

    // warp mapping: img = wid/2; m-tiles 2*(wid&1)+{0,1}; rows r=mt*16+g
    const int img  = wid >> 1;
    const int mtb  = (wid & 1) * 2;
    uint32_t bA[2][2];
#pragma unroll
    for (int mt = 0; mt < 2; mt++) {
        int r = (mtb + mt) * 16 + g;
        int p0 = min(r, 48);
        int p1 = min(r + 8, 48);
        bA[mt][0] = A0 + (uint32_t)((img * 5508 + ((p0 / 7) * 9 + p0 % 7) * 68) * 4)
                    + t * 4;
        bA[mt][1] = A0 + (uint32_t)((img * 5508 + ((p1 / 7) * 9 + p1 % 7) * 68) * 4)
                    + t * 4;
    }
    const uint32_t wfl = ln * 8;

    float acc[2][8][4];
#pragma unroll
    for (int mt = 0; mt < 2; mt++)
#pragma unroll
        for (int nt = 0; nt < 8; nt++)
#pragma unroll
            for (int j = 0; j < 4; j++) acc[mt][nt][j] = 0.0f;

    for (int tap = 0; tap < 9; tap++) {
        const uint32_t toff = (uint32_t)(((tap / 3) * 9 + tap % 3) * 272);
        const uint32_t wcur = W0 + (uint32_t)((tap & 1) * 16384) + wfl;

        // prefetch next slab into registers
        float4 n0, n1, n2, n3;
        if (tap < 8) {
            const float4* src = (const float4*)(g_w3f + (tap + 1) * 4096) + tid * 4;
            n0 = src[0]; n1 = src[1]; n2 = src[2]; n3 = src[3];
        }

#pragma unroll
        for (int ks = 0; ks < 8; ks++) {
            uint32_t a[2][4];
#pragma unroll
            for (int mt = 0; mt < 2; mt++) {
                uint32_t c0 = bA[mt][0] + toff + ks * 32;
                uint32_t c1 = bA[mt][1] + toff + ks * 32;
                a[mt][0] = lds_u32(c0);
                a[mt][1] = lds_u32(c1);
                a[mt][2] = lds_u32(c0 + 16);
                a[mt][3] = lds_u32(c1 + 16);
            }
            const uint32_t wks = wcur + ks * 2048;
#pragma unroll
            for (int nt = 0; nt < 8; nt++) {
                uint32_t b0, b1;
                lds_v2u(wks + nt * 256, b0, b1);
                mma16n8k8(acc[0][nt], a[0][0], a[0][1], a[0][2], a[0][3], b0, b1);
                mma16n8k8(acc[1][nt], a[1][0], a[1][1], a[1][2], a[1][3], b0, b1);
            }
        }

        if (tap < 8) {
            uint32_t dst = W0 + (uint32_t)(((tap + 1) & 1) * 16384) + tid * 64;
            sts_v4(dst,      n0); sts_v4(dst + 16, n1);
            sts_v4(dst + 32, n2); sts_v4(dst + 48, n3);
        }
        __syncthreads();
    }

    // epilogue: bias + relu -> g_c3 NHWC, direct float2 stores
    float bs0[8], bs1[8];
#pragma unroll
    for (int nt = 0; nt < 8; nt++) {
        bs0[nt] = lds_f32(BS + (nt * 8 + 2 * t) * 4);
        bs1[nt] = lds_f32(BS + (nt * 8 + 2 * t + 1) * 4);
    }
    float* cb = g_c3 + (size_t)(b0 + img) * 3136;
#pragma unroll
    for (int mt = 0; mt < 2; mt++) {
        int r0 = (mtb + mt) * 16 + g;
        int r1 = r0 + 8;
#pragma unroll
        for (int nt = 0; nt < 8; nt++) {
            int c = nt * 8 + 2 * t;
            if (r0 < 49) {
                float2 o;
                o.x = fmaxf(acc[mt][nt][0] + bs0[nt], 0.0f);
                o.y = fmaxf(acc[mt][nt][1] + bs1[nt], 0.0f);
                *reinterpret_cast<float2*>(cb + r0 * 64 + c) = o;
            }
            if (r1 < 49) {
                float2 o;
                o.x = fmaxf(acc[mt][nt][2] + bs0[nt], 0.0f);
                o.y = fmaxf(acc[mt][nt][3] + bs1[nt], 0.0f);
                *reinterpret_cast<float2*>(cb + r1 * 64 + c) = o;
            }
        }
    }
}

// ---------------------------------------------------------------------------
// K3b: dense1 (3136->64, relu) + dense2(64->10) + softmax. (R7, unchanged)
// ---------------------------------------------------------------------------
__global__ void __launch_bounds__(256)
k3b_dense(const float* __restrict__ wd1, const float* __restrict__ bd1,
          const float* __restrict__ wd2, const float* __restrict__ bd2,
          float* __restrict__ out) {
    __shared__ float As[8 * 196];
    __shared__ float Ws[196 * 64];
    __shared__ float hs[8 * 64];

    const int tid = threadIdx.x;
    const int b0  = blockIdx.x * 8;
    const int bl  = tid >> 5;
    const int ocp = tid & 31;

    unsigned long long acc0 = 0ULL, acc1 = 0ULL;

    for (int ch = 0; ch < 16; ch++) {
        for (int i = tid; i < 392; i += 256) {
            int r = i / 49, c = i % 49;
            reinterpret_cast<float4*>(As + r * 196)[c] =
                *reinterpret_cast<const float4*>(
                    g_c3 + (size_t)(b0 + r) * 3136 + ch * 196 + c * 4);
        }
        const float4* src = reinterpret_cast<const float4*>(
            wd1 + (size_t)(ch * 196) * 64);
        for (int i = tid; i < 3136; i += 256)
            reinterpret_cast<float4*>(Ws)[i] = src[i];
        __syncthreads();

        const float* arow = As + bl * 196;
        const unsigned long long* wp =
            reinterpret_cast<const unsigned long long*>(Ws) + ocp;
#pragma unroll 2
        for (int k = 0; k < 196; k += 2) {
            ffma2(acc0, pack2(arow[k]),     wp[(size_t)k * 32]);
            ffma2(acc1, pack2(arow[k + 1]), wp[(size_t)(k + 1) * 32]);
        }
        __syncthreads();
    }

    {
        float v0, v1, u0, u1;
        unpack2(acc0, v0, v1);
        unpack2(acc1, u0, u1);
        int oc0 = ocp * 2;
        hs[bl * 64 + oc0]     = fmaxf(v0 + u0 + bd1[oc0],     0.0f);
        hs[bl * 64 + oc0 + 1] = fmaxf(v1 + u1 + bd1[oc0 + 1], 0.0f);
    }
    __syncthreads();

    if (tid < 8) {
        const float* h = hs + tid * 64;
        float lg[10];
#pragma unroll
        for (int c = 0; c < 10; c++) {
            float s = bd2[c];
#pragma unroll
            for (int j = 0; j < 64; j++)
                s = fmaf(h[j], wd2[j * 10 + c], s);
            lg[c] = s;
        }
        float m = lg[0];
#pragma unroll
        for (int c = 1; c < 10; c++) m = fmaxf(m, lg[c]);
        float se = 0.0f;
#pragma unroll
        for (int c = 0; c < 10; c++) { lg[c] = expf(lg[c] - m); se += lg[c]; }
        float inv = 1.0f / se;
        float* o = out + (size_t)(b0 + tid) * 10;
#pragma unroll
        for (int c = 0; c < 10; c++) o[c] = lg[c] * inv;
    }
}

// ---------------------------------------------------------------------------
extern "C" void kernel_launch(void* const* d_in, const int* in_sizes, int n_in,
                              void* d_out, int out_size) {
    const float* x   = (const float*)d_in[0];
    const float* w1  = (const float*)d_in[1];
    const float* b1  = (const float*)d_in[2];
    const float* w2  = (const float*)d_in[3];
    const float* b2  = (const float*)d_in[4];
    const float* w3  = (const float*)d_in[5];
    const float* b3  = (const float*)d_in[6];
    const float* wd1 = (const float*)d_in[7];
    const float* bd1 = (const float*)d_in[8];
    const float* wd2 = (const float*)d_in[9];
    const float* bd2 = (const float*)d_in[10];
    float* out = (float*)d_out;

    cudaFuncSetAttribute(k2_conv2_mma,  cudaFuncAttributeMaxDynamicSharedMemorySize, K2_SMEM);
    cudaFuncSetAttribute(k3a_conv3_mma, cudaFuncAttributeMaxDynamicSharedMemorySize, K3_SMEM);

    k0_prep<<<216, 256>>>(w2, w3);
    k1_conv1<<<BATCH, 256>>>(x, w1, b1);
    k2_conv2_mma<<<BATCH, 256, K2_SMEM>>>(b2);
    k3a_conv3_mma<<<BATCH / 4, 256, K3_SMEM>>>(b3);
    k3b_dense<<<BATCH / 8, 256>>>(wd1, bd1, wd2, bd2, out);
}